// round 6
// baseline (speedup 1.0000x reference)
#include <cuda_runtime.h>
#include <cuda_fp16.h>
#include <math.h>

constexpr int BB = 8;
constexpr int TT = 128;
constexpr int NN = 256;
constexpr int FF = 128;
constexpr int MTOT = BB * TT * NN;   // 262144
constexpr int HP = 136;              // smem half pitch (padded)

// -------- scratch (device globals) --------
__device__ __half g_attn[MTOT * FF];

// ------------------- mma.sync helpers -------------------
__device__ __forceinline__ void ldsm4(unsigned& r0, unsigned& r1, unsigned& r2, unsigned& r3, unsigned addr) {
    asm volatile("ldmatrix.sync.aligned.m8n8.x4.shared.b16 {%0,%1,%2,%3},[%4];"
                 : "=r"(r0), "=r"(r1), "=r"(r2), "=r"(r3) : "r"(addr));
}
__device__ __forceinline__ void ldsm4t(unsigned& r0, unsigned& r1, unsigned& r2, unsigned& r3, unsigned addr) {
    asm volatile("ldmatrix.sync.aligned.m8n8.x4.trans.shared.b16 {%0,%1,%2,%3},[%4];"
                 : "=r"(r0), "=r"(r1), "=r"(r2), "=r"(r3) : "r"(addr));
}
__device__ __forceinline__ void mma16816(float* cc, const unsigned* aa, const unsigned* bb) {
    asm volatile("mma.sync.aligned.m16n8k16.row.col.f32.f16.f16.f32 "
                 "{%0,%1,%2,%3},{%4,%5,%6,%7},{%8,%9},{%0,%1,%2,%3};"
                 : "+f"(cc[0]), "+f"(cc[1]), "+f"(cc[2]), "+f"(cc[3])
                 : "r"(aa[0]), "r"(aa[1]), "r"(aa[2]), "r"(aa[3]), "r"(bb[0]), "r"(bb[1]));
}
__device__ __forceinline__ unsigned sptr(const void* ptr) {
    return (unsigned)__cvta_generic_to_shared(ptr);
}
__device__ __forceinline__ unsigned pack2(float a, float b) {
    __half2 h = __floats2half2_rn(a, b);
    return *reinterpret_cast<unsigned*>(&h);
}

// 128x128x128 tile GEMM: Amat [128 rows][HP] f16, Bmat [128 k][HP] f16 holding W[K][N].
// 8 warps: warp (wy,wx) computes 64x32.
__device__ __forceinline__ void mma_tile(const __half* Amat, const __half* Bmat, float acc[4][4][4]) {
    const int lane = threadIdx.x & 31;
    const int warp = threadIdx.x >> 5;
    const int wy = warp >> 2;
    const int wx = warp & 3;
    const int r16 = lane & 15;
    const int hi8 = (lane >> 4) * 8;
    #pragma unroll
    for (int k0 = 0; k0 < 128; k0 += 16) {
        unsigned afrag[4][4];
        #pragma unroll
        for (int i = 0; i < 4; ++i) {
            unsigned addr = sptr(Amat + (wy * 64 + i * 16 + r16) * HP + k0 + hi8);
            ldsm4(afrag[i][0], afrag[i][1], afrag[i][2], afrag[i][3], addr);
        }
        unsigned bfrag[4][2];
        #pragma unroll
        for (int jj = 0; jj < 2; ++jj) {
            unsigned addr = sptr(Bmat + (k0 + r16) * HP + wx * 32 + jj * 16 + hi8);
            unsigned t0, t1, t2, t3;
            ldsm4t(t0, t1, t2, t3, addr);
            bfrag[jj * 2 + 0][0] = t0; bfrag[jj * 2 + 0][1] = t1;
            bfrag[jj * 2 + 1][0] = t2; bfrag[jj * 2 + 1][1] = t3;
        }
        #pragma unroll
        for (int i = 0; i < 4; ++i)
            #pragma unroll
            for (int j = 0; j < 4; ++j)
                mma16816(acc[i][j], afrag[i], bfrag[j]);
    }
}

// writeback accumulators (+bias, optional relu) into an f16 smem tile [128][HP]
__device__ __forceinline__ void store_tile(__half* dst, float acc[4][4][4],
                                           const float* __restrict__ bias, bool doRelu) {
    const int lane = threadIdx.x & 31;
    const int warp = threadIdx.x >> 5;
    const int wy = warp >> 2;
    const int wx = warp & 3;
    const int gid = lane >> 2;
    const int tig = lane & 3;
    #pragma unroll
    for (int i = 0; i < 4; ++i) {
        int row = wy * 64 + i * 16 + gid;
        #pragma unroll
        for (int j = 0; j < 4; ++j) {
            int col = wx * 32 + j * 8 + tig * 2;
            float2 bv = *(const float2*)(bias + col);
            float o0 = acc[i][j][0] + bv.x;
            float o1 = acc[i][j][1] + bv.y;
            float o2 = acc[i][j][2] + bv.x;
            float o3 = acc[i][j][3] + bv.y;
            if (doRelu) {
                o0 = fmaxf(o0, 0.f); o1 = fmaxf(o1, 0.f);
                o2 = fmaxf(o2, 0.f); o3 = fmaxf(o3, 0.f);
            }
            *(__half2*)(dst + row * HP + col)       = __floats2half2_rn(o0, o1);
            *(__half2*)(dst + (row + 8) * HP + col) = __floats2half2_rn(o2, o3);
        }
    }
}

// =====================================================================
// attention warp body: warp w owns rows t in [16w,16w+16), s-tile-pairs jp<=w.
// =====================================================================
template<int NP>
__device__ __forceinline__ void attn_warp(const __half* Qs, const __half* Ks, const __half* Vs,
                                          int base, int w, int lane)
{
    const int r16 = lane & 15;
    const int hi8 = (lane >> 4) * 8;
    const int gid = lane >> 2;
    const int tig = lane & 3;

    unsigned aq[8][4];
    #pragma unroll
    for (int k = 0; k < 8; ++k) {
        unsigned addr = sptr(Qs + (16 * w + r16) * HP + k * 16 + hi8);
        ldsm4(aq[k][0], aq[k][1], aq[k][2], aq[k][3], addr);
    }

    float c[2 * NP][4];
    #pragma unroll
    for (int js = 0; js < 2 * NP; ++js) {
        c[js][0] = 0.f; c[js][1] = 0.f; c[js][2] = 0.f; c[js][3] = 0.f;
    }
    #pragma unroll
    for (int jp = 0; jp < NP; ++jp) {
        #pragma unroll
        for (int k = 0; k < 8; ++k) {
            unsigned t0, t1, t2, t3;
            unsigned addr = sptr(Ks + (16 * jp + r16) * HP + k * 16 + hi8);
            ldsm4(t0, t1, t2, t3, addr);
            unsigned bE[2] = { t0, t2 };
            unsigned bO[2] = { t1, t3 };
            mma16816(c[2 * jp],     aq[k], bE);
            mma16816(c[2 * jp + 1], aq[k], bO);
        }
    }

    const float scale = 0.08838834764831845f;   // 1/sqrt(128)
    const int tlo = 16 * w + gid;
    const int thi = tlo + 8;
    float mlo = -1e30f, mhi = -1e30f;
    #pragma unroll
    for (int js = 0; js < 2 * NP; ++js) {
        int s0 = 8 * js + 2 * tig;
        int s1 = s0 + 1;
        c[js][0] *= scale; c[js][1] *= scale;
        c[js][2] *= scale; c[js][3] *= scale;
        if (js >= 2 * NP - 2) {          // diagonal block: causal mask
            if (s0 > tlo) c[js][0] = -1e30f;
            if (s1 > tlo) c[js][1] = -1e30f;
            if (s0 > thi) c[js][2] = -1e30f;
            if (s1 > thi) c[js][3] = -1e30f;
        }
        mlo = fmaxf(mlo, fmaxf(c[js][0], c[js][1]));
        mhi = fmaxf(mhi, fmaxf(c[js][2], c[js][3]));
    }
    #pragma unroll
    for (int o = 1; o <= 2; o <<= 1) {
        mlo = fmaxf(mlo, __shfl_xor_sync(0xffffffffu, mlo, o));
        mhi = fmaxf(mhi, __shfl_xor_sync(0xffffffffu, mhi, o));
    }
    float slo = 0.f, shi = 0.f;
    #pragma unroll
    for (int js = 0; js < 2 * NP; ++js) {
        c[js][0] = __expf(c[js][0] - mlo);
        c[js][1] = __expf(c[js][1] - mlo);
        c[js][2] = __expf(c[js][2] - mhi);
        c[js][3] = __expf(c[js][3] - mhi);
        slo += c[js][0] + c[js][1];
        shi += c[js][2] + c[js][3];
    }
    #pragma unroll
    for (int o = 1; o <= 2; o <<= 1) {
        slo += __shfl_xor_sync(0xffffffffu, slo, o);
        shi += __shfl_xor_sync(0xffffffffu, shi, o);
    }
    const float invlo = 1.f / slo;
    const float invhi = 1.f / shi;

    float ov[16][4];
    #pragma unroll
    for (int jt = 0; jt < 16; ++jt) {
        ov[jt][0] = 0.f; ov[jt][1] = 0.f; ov[jt][2] = 0.f; ov[jt][3] = 0.f;
    }
    #pragma unroll
    for (int ks = 0; ks < NP; ++ks) {
        unsigned ap[4];
        ap[0] = pack2(c[2 * ks][0],     c[2 * ks][1]);
        ap[1] = pack2(c[2 * ks][2],     c[2 * ks][3]);
        ap[2] = pack2(c[2 * ks + 1][0], c[2 * ks + 1][1]);
        ap[3] = pack2(c[2 * ks + 1][2], c[2 * ks + 1][3]);
        #pragma unroll
        for (int jf = 0; jf < 8; ++jf) {
            unsigned t0, t1, t2, t3;
            unsigned addr = sptr(Vs + (16 * ks + r16) * HP + jf * 16 + hi8);
            ldsm4t(t0, t1, t2, t3, addr);
            unsigned b0[2] = { t0, t1 };
            unsigned b1[2] = { t2, t3 };
            mma16816(ov[2 * jf],     ap, b0);
            mma16816(ov[2 * jf + 1], ap, b1);
        }
    }

    __half* olo = g_attn + (base + tlo * NN) * FF;
    __half* ohi = g_attn + (base + thi * NN) * FF;
    #pragma unroll
    for (int jt = 0; jt < 16; ++jt) {
        int col = jt * 8 + tig * 2;
        *(__half2*)(olo + col) = __floats2half2_rn(ov[jt][0] * invlo, ov[jt][1] * invlo);
        *(__half2*)(ohi + col) = __floats2half2_rn(ov[jt][2] * invhi, ov[jt][3] * invhi);
    }
}

// =====================================================================
// Kernel 1 (fused qkv + attention), one head (b,n) per CTA.
//   q = (xl+te)@Wq+bq ; kh = relu((xh+te)@Wkh+bkh) ; vh = relu((xh+te)@Wvh+bvh)
//   attn = causal_softmax(q kh^T / sqrt(128)) @ vh   -> g_attn (fp16)
// =====================================================================
__global__ __launch_bounds__(256) void fused_attn_kernel(
    const float* __restrict__ xl, const float* __restrict__ xh,
    const float* __restrict__ te,
    const float* __restrict__ Wq,  const float* __restrict__ bq,
    const float* __restrict__ Wkh, const float* __restrict__ bkh,
    const float* __restrict__ Wvh, const float* __restrict__ bvh)
{
    extern __shared__ char smraw[];
    __half* Qs = (__half*)smraw;         // 128*HP
    __half* Ks = Qs + 128 * HP;
    __half* Vs = Ks + 128 * HP;
    __half* As = Vs + 128 * HP;          // X tile (f16)
    __half* Bs = As + 128 * HP;          // weight tile (f16)

    const int head = blockIdx.x;
    const int bidx = head >> 8;
    const int nidx = head & 255;
    const int base = bidx * TT * NN + nidx;   // row index at t=0; row(t)=base+t*NN

    const int tid = threadIdx.x;
    const int w = tid >> 5;
    const int lane = tid & 31;

    const float4* xl4 = (const float4*)xl;
    const float4* xh4 = (const float4*)xh;
    const float4* te4 = (const float4*)te;

    // ---- phase 1: As = xl(head rows)+te, Bs = Wq ----
    for (int v = tid; v < 4096; v += 256) {
        int row = v >> 5;
        int c4 = v & 31;
        float4 aval = xl4[(base + row * NN) * 32 + c4];
        float4 tval = te4[(bidx * TT + row) * 32 + c4];
        __half2* adst = (__half2*)(As + row * HP + c4 * 4);
        adst[0] = __floats2half2_rn(aval.x + tval.x, aval.y + tval.y);
        adst[1] = __floats2half2_rn(aval.z + tval.z, aval.w + tval.w);
        float4 wval = ((const float4*)Wq)[v];
        __half2* wdst = (__half2*)(Bs + row * HP + c4 * 4);
        wdst[0] = __floats2half2_rn(wval.x, wval.y);
        wdst[1] = __floats2half2_rn(wval.z, wval.w);
    }
    __syncthreads();

    {
        float acc[4][4][4] = {};
        mma_tile(As, Bs, acc);
        store_tile(Qs, acc, bq, false);
    }
    __syncthreads();   // all reads of As/Bs done before overwrite

    // ---- phase 2: As = xh(head rows)+te, Bs = Wkh ----
    for (int v = tid; v < 4096; v += 256) {
        int row = v >> 5;
        int c4 = v & 31;
        float4 aval = xh4[(base + row * NN) * 32 + c4];
        float4 tval = te4[(bidx * TT + row) * 32 + c4];
        __half2* adst = (__half2*)(As + row * HP + c4 * 4);
        adst[0] = __floats2half2_rn(aval.x + tval.x, aval.y + tval.y);
        adst[1] = __floats2half2_rn(aval.z + tval.z, aval.w + tval.w);
        float4 wval = ((const float4*)Wkh)[v];
        __half2* wdst = (__half2*)(Bs + row * HP + c4 * 4);
        wdst[0] = __floats2half2_rn(wval.x, wval.y);
        wdst[1] = __floats2half2_rn(wval.z, wval.w);
    }
    __syncthreads();

    {
        float acc[4][4][4] = {};
        mma_tile(As, Bs, acc);
        store_tile(Ks, acc, bkh, true);
    }
    __syncthreads();   // Bs reads done before overwrite (As stays = xh+te)

    // ---- phase 3: Bs = Wvh ----
    for (int v = tid; v < 4096; v += 256) {
        int row = v >> 5;
        int c4 = v & 31;
        float4 wval = ((const float4*)Wvh)[v];
        __half2* wdst = (__half2*)(Bs + row * HP + c4 * 4);
        wdst[0] = __floats2half2_rn(wval.x, wval.y);
        wdst[1] = __floats2half2_rn(wval.z, wval.w);
    }
    __syncthreads();

    {
        float acc[4][4][4] = {};
        mma_tile(As, Bs, acc);
        store_tile(Vs, acc, bvh, true);
    }
    __syncthreads();   // Q/K/V complete & visible to all warps

    // ---- phase 4: causal attention ----
    switch (w) {
        case 0: attn_warp<1>(Qs, Ks, Vs, base, 0, lane); break;
        case 1: attn_warp<2>(Qs, Ks, Vs, base, 1, lane); break;
        case 2: attn_warp<3>(Qs, Ks, Vs, base, 2, lane); break;
        case 3: attn_warp<4>(Qs, Ks, Vs, base, 3, lane); break;
        case 4: attn_warp<5>(Qs, Ks, Vs, base, 4, lane); break;
        case 5: attn_warp<6>(Qs, Ks, Vs, base, 5, lane); break;
        case 6: attn_warp<7>(Qs, Ks, Vs, base, 6, lane); break;
        default: attn_warp<8>(Qs, Ks, Vs, base, 7, lane); break;
    }
}

// =====================================================================
// Kernel 2 (fused proj+ffn):
//   val = attn@Wo + bo + (xl+te); ln1 = LN(val)
//   h = relu(ln1@Wf1+bf1); h2 = h@Wf2+bf2; out = LN(h2 + ln1)
// =====================================================================
__global__ __launch_bounds__(256) void tail_kernel(
    float* __restrict__ outp,
    const float* __restrict__ xl, const float* __restrict__ te,
    const float* __restrict__ Wo, const float* __restrict__ bo,
    const float* __restrict__ Wf1, const float* __restrict__ bf1,
    const float* __restrict__ Wf2, const float* __restrict__ bf2)
{
    extern __shared__ char smraw[];
    __half* Amat = (__half*)smraw;              // data tile (attn -> ln1 -> h)
    __half* W0m = Amat + 128 * HP;
    __half* W1m = Amat + 2 * 128 * HP;
    __half* W2m = Amat + 3 * 128 * HP;
    float*  Cmat = (float*)(Amat + 4 * 128 * HP);   // fp32 residual / staging [128][132]

    const int m0 = blockIdx.x * 128;
    const int tid = threadIdx.x;

    for (int v = tid; v < 2048; v += 256) {           // attn tile: direct f16 copy
        int row = v >> 4;
        int q16 = v & 15;
        ((uint4*)(Amat + row * HP))[q16] = ((const uint4*)(g_attn + (m0 + row) * FF))[q16];
    }
    const float4* wo4 = (const float4*)Wo;
    const float4* wf14 = (const float4*)Wf1;
    const float4* wf24 = (const float4*)Wf2;
    const float4* xl4 = (const float4*)xl;
    const float4* te4 = (const float4*)(te + (m0 / NN) * FF);
    for (int v = tid; v < 4096; v += 256) {
        int row = v >> 5;
        int c4 = v & 31;
        float4 w0 = wo4[v];
        __half2* d0 = (__half2*)(W0m + row * HP + c4 * 4);
        d0[0] = __floats2half2_rn(w0.x, w0.y);
        d0[1] = __floats2half2_rn(w0.z, w0.w);
        float4 w1 = wf14[v];
        __half2* d1 = (__half2*)(W1m + row * HP + c4 * 4);
        d1[0] = __floats2half2_rn(w1.x, w1.y);
        d1[1] = __floats2half2_rn(w1.z, w1.w);
        float4 w2 = wf24[v];
        __half2* d2 = (__half2*)(W2m + row * HP + c4 * 4);
        d2[0] = __floats2half2_rn(w2.x, w2.y);
        d2[1] = __floats2half2_rn(w2.z, w2.w);
        float4 aval = xl4[(m0 + row) * 32 + c4];
        float4 tval = te4[c4];
        ((float4*)(Cmat + row * 132))[c4] =
            make_float4(aval.x + tval.x, aval.y + tval.y, aval.z + tval.z, aval.w + tval.w);
    }
    __syncthreads();

    const int lane = tid & 31;
    const int warp = tid >> 5;
    const int wy = warp >> 2;
    const int wx = warp & 3;
    const int gid = lane >> 2;
    const int tig = lane & 3;

    // ---- proj GEMM ----
    float acc[4][4][4] = {};
    mma_tile(Amat, W0m, acc);
    __syncthreads();   // Amat reads done

    #pragma unroll
    for (int i = 0; i < 4; ++i) {
        int row = wy * 64 + i * 16 + gid;
        #pragma unroll
        for (int j = 0; j < 4; ++j) {
            int col = wx * 32 + j * 8 + tig * 2;
            float2 bv = *(const float2*)(bo + col);
            Cmat[row * 132 + col]           += acc[i][j][0] + bv.x;
            Cmat[row * 132 + col + 1]       += acc[i][j][1] + bv.y;
            Cmat[(row + 8) * 132 + col]     += acc[i][j][2] + bv.x;
            Cmat[(row + 8) * 132 + col + 1] += acc[i][j][3] + bv.y;
        }
    }
    __syncthreads();

    // ---- LayerNorm 1 ----
    for (int row = warp; row < 128; row += 8) {
        float4 vval = ((const float4*)(Cmat + row * 132))[lane];
        float s1 = vval.x + vval.y + vval.z + vval.w;
        float s2 = vval.x * vval.x + vval.y * vval.y + vval.z * vval.z + vval.w * vval.w;
        #pragma unroll
        for (int o = 16; o; o >>= 1) {
            s1 += __shfl_xor_sync(0xffffffffu, s1, o);
            s2 += __shfl_xor_sync(0xffffffffu, s2, o);
        }
        float mean = s1 * 0.0078125f;
        float var = s2 * 0.0078125f - mean * mean;
        float rsd = rsqrtf(var + 1e-5f);
        float n0 = (vval.x - mean) * rsd;
        float n1 = (vval.y - mean) * rsd;
        float n2 = (vval.z - mean) * rsd;
        float n3 = (vval.w - mean) * rsd;
        ((float4*)(Cmat + row * 132))[lane] = make_float4(n0, n1, n2, n3);
        __half2* adst = (__half2*)(Amat + row * HP + lane * 4);
        adst[0] = __floats2half2_rn(n0, n1);
        adst[1] = __floats2half2_rn(n2, n3);
    }
    __syncthreads();

    // ---- FFN GEMM 1 ----
    float acc2[4][4][4] = {};
    mma_tile(Amat, W1m, acc2);
    __syncthreads();   // Amat reads done before overwrite with H

    #pragma unroll
    for (int i = 0; i < 4; ++i) {
        int row = wy * 64 + i * 16 + gid;
        #pragma unroll
        for (int j = 0; j < 4; ++j) {
            int col = wx * 32 + j * 8 + tig * 2;
            float2 bv = *(const float2*)(bf1 + col);
            *(__half2*)(Amat + row * HP + col) =
                __floats2half2_rn(fmaxf(acc2[i][j][0] + bv.x, 0.f), fmaxf(acc2[i][j][1] + bv.y, 0.f));
            *(__half2*)(Amat + (row + 8) * HP + col) =
                __floats2half2_rn(fmaxf(acc2[i][j][2] + bv.x, 0.f), fmaxf(acc2[i][j][3] + bv.y, 0.f));
        }
    }
    __syncthreads();

    // ---- FFN GEMM 2 ----
    float acc3[4][4][4] = {};
    mma_tile(Amat, W2m, acc3);

    #pragma unroll
    for (int i = 0; i < 4; ++i) {
        int row = wy * 64 + i * 16 + gid;
        #pragma unroll
        for (int j = 0; j < 4; ++j) {
            int col = wx * 32 + j * 8 + tig * 2;
            float2 bv = *(const float2*)(bf2 + col);
            Cmat[row * 132 + col]           += acc3[i][j][0] + bv.x;
            Cmat[row * 132 + col + 1]       += acc3[i][j][1] + bv.y;
            Cmat[(row + 8) * 132 + col]     += acc3[i][j][2] + bv.x;
            Cmat[(row + 8) * 132 + col + 1] += acc3[i][j][3] + bv.y;
        }
    }
    __syncthreads();

    // ---- LayerNorm 2 -> output ----
    for (int row = warp; row < 128; row += 8) {
        float4 vval = ((const float4*)(Cmat + row * 132))[lane];
        float s1 = vval.x + vval.y + vval.z + vval.w;
        float s2 = vval.x * vval.x + vval.y * vval.y + vval.z * vval.z + vval.w * vval.w;
        #pragma unroll
        for (int o = 16; o; o >>= 1) {
            s1 += __shfl_xor_sync(0xffffffffu, s1, o);
            s2 += __shfl_xor_sync(0xffffffffu, s2, o);
        }
        float mean = s1 * 0.0078125f;
        float var = s2 * 0.0078125f - mean * mean;
        float rsd = rsqrtf(var + 1e-5f);
        ((float4*)(outp + (m0 + row) * FF))[lane] =
            make_float4((vval.x - mean) * rsd, (vval.y - mean) * rsd,
                        (vval.z - mean) * rsd, (vval.w - mean) * rsd);
    }
}

// =====================================================================
extern "C" void kernel_launch(void* const* d_in, const int* in_sizes, int n_in,
                              void* d_out, int out_size)
{
    const float* xl  = (const float*)d_in[0];
    const float* xh  = (const float*)d_in[1];
    const float* te  = (const float*)d_in[2];
    const float* Wq  = (const float*)d_in[3];
    const float* bq  = (const float*)d_in[4];
    const float* Wkh = (const float*)d_in[5];
    const float* bkh = (const float*)d_in[6];
    const float* Wvh = (const float*)d_in[7];
    const float* bvh = (const float*)d_in[8];
    const float* Wo  = (const float*)d_in[9];
    const float* bo  = (const float*)d_in[10];
    const float* Wf1 = (const float*)d_in[11];
    const float* bf1 = (const float*)d_in[12];
    const float* Wf2 = (const float*)d_in[13];
    const float* bf2 = (const float*)d_in[14];
    float* outp = (float*)d_out;

    const int smFused = 5 * 128 * HP * 2;                     // 174080
    const int smTail  = 4 * 128 * HP * 2 + 128 * 132 * 4;     // 206848

    cudaFuncSetAttribute(fused_attn_kernel, cudaFuncAttributeMaxDynamicSharedMemorySize, smFused);
    cudaFuncSetAttribute(tail_kernel,       cudaFuncAttributeMaxDynamicSharedMemorySize, smTail);

    fused_attn_kernel<<<BB * NN, 256, smFused>>>(xl, xh, te, Wq, bq, Wkh, bkh, Wvh, bvh);
    tail_kernel<<<MTOT / 128, 256, smTail>>>(outp, xl, te, Wo, bo, Wf1, bf1, Wf2, bf2);
}

// round 7
// speedup vs baseline: 1.5310x; 1.5310x over previous
#include <cuda_runtime.h>
#include <cuda_fp16.h>
#include <math.h>

constexpr int BB = 8;
constexpr int TT = 128;
constexpr int NN = 256;
constexpr int FF = 128;
constexpr int MTOT = BB * TT * NN;   // 262144
constexpr int HP = 136;              // smem half pitch (padded)

// -------- scratch (device globals) --------
__device__ __half g_attn[MTOT * FF];
__device__ __align__(16) __half g_wq16 [FF * FF];
__device__ __align__(16) __half g_wkh16[FF * FF];
__device__ __align__(16) __half g_wvh16[FF * FF];
__device__ __align__(16) __half g_wo16 [FF * FF];
__device__ __align__(16) __half g_wf116[FF * FF];
__device__ __align__(16) __half g_wf216[FF * FF];

// ------------------- mma.sync helpers -------------------
__device__ __forceinline__ void ldsm4(unsigned& r0, unsigned& r1, unsigned& r2, unsigned& r3, unsigned addr) {
    asm volatile("ldmatrix.sync.aligned.m8n8.x4.shared.b16 {%0,%1,%2,%3},[%4];"
                 : "=r"(r0), "=r"(r1), "=r"(r2), "=r"(r3) : "r"(addr));
}
__device__ __forceinline__ void ldsm4t(unsigned& r0, unsigned& r1, unsigned& r2, unsigned& r3, unsigned addr) {
    asm volatile("ldmatrix.sync.aligned.m8n8.x4.trans.shared.b16 {%0,%1,%2,%3},[%4];"
                 : "=r"(r0), "=r"(r1), "=r"(r2), "=r"(r3) : "r"(addr));
}
__device__ __forceinline__ void mma16816(float* cc, const unsigned* aa, const unsigned* bb) {
    asm volatile("mma.sync.aligned.m16n8k16.row.col.f32.f16.f16.f32 "
                 "{%0,%1,%2,%3},{%4,%5,%6,%7},{%8,%9},{%0,%1,%2,%3};"
                 : "+f"(cc[0]), "+f"(cc[1]), "+f"(cc[2]), "+f"(cc[3])
                 : "r"(aa[0]), "r"(aa[1]), "r"(aa[2]), "r"(aa[3]), "r"(bb[0]), "r"(bb[1]));
}
__device__ __forceinline__ unsigned sptr(const void* ptr) {
    return (unsigned)__cvta_generic_to_shared(ptr);
}
__device__ __forceinline__ unsigned pack2(float a, float b) {
    __half2 h = __floats2half2_rn(a, b);
    return *reinterpret_cast<unsigned*>(&h);
}

// 128x128x128 tile GEMM, 8 warps, warp (wy,wx) computes 64x32.
__device__ __forceinline__ void mma_tile(const __half* Amat, const __half* Bmat, float acc[4][4][4]) {
    const int lane = threadIdx.x & 31;
    const int warp = threadIdx.x >> 5;
    const int wy = warp >> 2;
    const int wx = warp & 3;
    const int r16 = lane & 15;
    const int hi8 = (lane >> 4) * 8;
    #pragma unroll
    for (int k0 = 0; k0 < 128; k0 += 16) {
        unsigned afrag[4][4];
        #pragma unroll
        for (int i = 0; i < 4; ++i) {
            unsigned addr = sptr(Amat + (wy * 64 + i * 16 + r16) * HP + k0 + hi8);
            ldsm4(afrag[i][0], afrag[i][1], afrag[i][2], afrag[i][3], addr);
        }
        unsigned bfrag[4][2];
        #pragma unroll
        for (int jj = 0; jj < 2; ++jj) {
            unsigned addr = sptr(Bmat + (k0 + r16) * HP + wx * 32 + jj * 16 + hi8);
            unsigned t0, t1, t2, t3;
            ldsm4t(t0, t1, t2, t3, addr);
            bfrag[jj * 2 + 0][0] = t0; bfrag[jj * 2 + 0][1] = t1;
            bfrag[jj * 2 + 1][0] = t2; bfrag[jj * 2 + 1][1] = t3;
        }
        #pragma unroll
        for (int i = 0; i < 4; ++i)
            #pragma unroll
            for (int j = 0; j < 4; ++j)
                mma16816(acc[i][j], afrag[i], bfrag[j]);
    }
}

// writeback accumulators (+bias, optional relu) into an f16 smem tile [128][HP]
__device__ __forceinline__ void store_tile(__half* dst, float acc[4][4][4],
                                           const float* __restrict__ bias, bool doRelu) {
    const int lane = threadIdx.x & 31;
    const int warp = threadIdx.x >> 5;
    const int wy = warp >> 2;
    const int wx = warp & 3;
    const int gid = lane >> 2;
    const int tig = lane & 3;
    #pragma unroll
    for (int i = 0; i < 4; ++i) {
        int row = wy * 64 + i * 16 + gid;
        #pragma unroll
        for (int j = 0; j < 4; ++j) {
            int col = wx * 32 + j * 8 + tig * 2;
            float2 bv = *(const float2*)(bias + col);
            float o0 = acc[i][j][0] + bv.x;
            float o1 = acc[i][j][1] + bv.y;
            float o2 = acc[i][j][2] + bv.x;
            float o3 = acc[i][j][3] + bv.y;
            if (doRelu) {
                o0 = fmaxf(o0, 0.f); o1 = fmaxf(o1, 0.f);
                o2 = fmaxf(o2, 0.f); o3 = fmaxf(o3, 0.f);
            }
            *(__half2*)(dst + row * HP + col)       = __floats2half2_rn(o0, o1);
            *(__half2*)(dst + (row + 8) * HP + col) = __floats2half2_rn(o2, o3);
        }
    }
}

// =====================================================================
// Kernel 0: one-time fp32 -> fp16 weight conversion.
// =====================================================================
__global__ void conv_kernel(const float* __restrict__ Wq, const float* __restrict__ Wkh,
                            const float* __restrict__ Wvh, const float* __restrict__ Wo,
                            const float* __restrict__ Wf1, const float* __restrict__ Wf2)
{
    int i = blockIdx.x * 256 + threadIdx.x;
    g_wq16[i]  = __float2half(Wq[i]);
    g_wkh16[i] = __float2half(Wkh[i]);
    g_wvh16[i] = __float2half(Wvh[i]);
    g_wo16[i]  = __float2half(Wo[i]);
    g_wf116[i] = __float2half(Wf1[i]);
    g_wf216[i] = __float2half(Wf2[i]);
}

// =====================================================================
// attention warp body: warp w owns rows t in [16w,16w+16), s-tile-pairs jp<=w.
// =====================================================================
template<int NP>
__device__ __forceinline__ void attn_warp(const __half* Qs, const __half* Ks, const __half* Vs,
                                          int base, int w, int lane)
{
    const int r16 = lane & 15;
    const int hi8 = (lane >> 4) * 8;
    const int gid = lane >> 2;
    const int tig = lane & 3;

    unsigned aq[8][4];
    #pragma unroll
    for (int k = 0; k < 8; ++k) {
        unsigned addr = sptr(Qs + (16 * w + r16) * HP + k * 16 + hi8);
        ldsm4(aq[k][0], aq[k][1], aq[k][2], aq[k][3], addr);
    }

    float c[2 * NP][4];
    #pragma unroll
    for (int js = 0; js < 2 * NP; ++js) {
        c[js][0] = 0.f; c[js][1] = 0.f; c[js][2] = 0.f; c[js][3] = 0.f;
    }
    #pragma unroll
    for (int jp = 0; jp < NP; ++jp) {
        #pragma unroll
        for (int k = 0; k < 8; ++k) {
            unsigned t0, t1, t2, t3;
            unsigned addr = sptr(Ks + (16 * jp + r16) * HP + k * 16 + hi8);
            ldsm4(t0, t1, t2, t3, addr);
            unsigned bE[2] = { t0, t2 };
            unsigned bO[2] = { t1, t3 };
            mma16816(c[2 * jp],     aq[k], bE);
            mma16816(c[2 * jp + 1], aq[k], bO);
        }
    }

    const float scale = 0.08838834764831845f;   // 1/sqrt(128)
    const int tlo = 16 * w + gid;
    const int thi = tlo + 8;
    float mlo = -1e30f, mhi = -1e30f;
    #pragma unroll
    for (int js = 0; js < 2 * NP; ++js) {
        int s0 = 8 * js + 2 * tig;
        int s1 = s0 + 1;
        c[js][0] *= scale; c[js][1] *= scale;
        c[js][2] *= scale; c[js][3] *= scale;
        if (js >= 2 * NP - 2) {          // diagonal block: causal mask
            if (s0 > tlo) c[js][0] = -1e30f;
            if (s1 > tlo) c[js][1] = -1e30f;
            if (s0 > thi) c[js][2] = -1e30f;
            if (s1 > thi) c[js][3] = -1e30f;
        }
        mlo = fmaxf(mlo, fmaxf(c[js][0], c[js][1]));
        mhi = fmaxf(mhi, fmaxf(c[js][2], c[js][3]));
    }
    #pragma unroll
    for (int o = 1; o <= 2; o <<= 1) {
        mlo = fmaxf(mlo, __shfl_xor_sync(0xffffffffu, mlo, o));
        mhi = fmaxf(mhi, __shfl_xor_sync(0xffffffffu, mhi, o));
    }
    float slo = 0.f, shi = 0.f;
    #pragma unroll
    for (int js = 0; js < 2 * NP; ++js) {
        c[js][0] = __expf(c[js][0] - mlo);
        c[js][1] = __expf(c[js][1] - mlo);
        c[js][2] = __expf(c[js][2] - mhi);
        c[js][3] = __expf(c[js][3] - mhi);
        slo += c[js][0] + c[js][1];
        shi += c[js][2] + c[js][3];
    }
    #pragma unroll
    for (int o = 1; o <= 2; o <<= 1) {
        slo += __shfl_xor_sync(0xffffffffu, slo, o);
        shi += __shfl_xor_sync(0xffffffffu, shi, o);
    }
    const float invlo = 1.f / slo;
    const float invhi = 1.f / shi;

    float ov[16][4];
    #pragma unroll
    for (int jt = 0; jt < 16; ++jt) {
        ov[jt][0] = 0.f; ov[jt][1] = 0.f; ov[jt][2] = 0.f; ov[jt][3] = 0.f;
    }
    #pragma unroll
    for (int ks = 0; ks < NP; ++ks) {
        unsigned ap[4];
        ap[0] = pack2(c[2 * ks][0],     c[2 * ks][1]);
        ap[1] = pack2(c[2 * ks][2],     c[2 * ks][3]);
        ap[2] = pack2(c[2 * ks + 1][0], c[2 * ks + 1][1]);
        ap[3] = pack2(c[2 * ks + 1][2], c[2 * ks + 1][3]);
        #pragma unroll
        for (int jf = 0; jf < 8; ++jf) {
            unsigned t0, t1, t2, t3;
            unsigned addr = sptr(Vs + (16 * ks + r16) * HP + jf * 16 + hi8);
            ldsm4t(t0, t1, t2, t3, addr);
            unsigned b0[2] = { t0, t1 };
            unsigned b1[2] = { t2, t3 };
            mma16816(ov[2 * jf],     ap, b0);
            mma16816(ov[2 * jf + 1], ap, b1);
        }
    }

    __half* olo = g_attn + (base + tlo * NN) * FF;
    __half* ohi = g_attn + (base + thi * NN) * FF;
    #pragma unroll
    for (int jt = 0; jt < 16; ++jt) {
        int col = jt * 8 + tig * 2;
        *(__half2*)(olo + col) = __floats2half2_rn(ov[jt][0] * invlo, ov[jt][1] * invlo);
        *(__half2*)(ohi + col) = __floats2half2_rn(ov[jt][2] * invhi, ov[jt][3] * invhi);
    }
}

// =====================================================================
// Kernel 1 (fused qkv + attention), one head (b,n) per CTA.
// Up-front staging of X1=xh+te, X2=xl+te, W0=Wkh, W1=Wvh; then
// K-mma and V-mma back-to-back; Q written into freed X1.
// =====================================================================
__global__ __launch_bounds__(256) void fused_attn_kernel(
    const float* __restrict__ xl, const float* __restrict__ xh,
    const float* __restrict__ te,
    const float* __restrict__ bq, const float* __restrict__ bkh,
    const float* __restrict__ bvh)
{
    extern __shared__ char smraw[];
    __half* X1 = (__half*)smraw;          // xh+te, later Q
    __half* X2 = X1 + 128 * HP;           // xl+te
    __half* W0 = X2 + 128 * HP;           // Wkh, later Wq
    __half* W1 = W0 + 128 * HP;           // Wvh
    __half* Ks = W1 + 128 * HP;
    __half* Vs = Ks + 128 * HP;           // total 6*34816 = 208896

    const int head = blockIdx.x;
    const int bidx = head >> 8;
    const int nidx = head & 255;
    const int base = bidx * TT * NN + nidx;   // row(t)=base+t*NN

    const int tid = threadIdx.x;
    const int w = tid >> 5;
    const int lane = tid & 31;

    const float4* xl4 = (const float4*)xl;
    const float4* xh4 = (const float4*)xh;
    const float4* te4 = (const float4*)te;

    // ---- stage everything up front ----
    for (int v = tid; v < 4096; v += 256) {
        int row = v >> 5;
        int c4 = v & 31;
        float4 tval = te4[(bidx * TT + row) * 32 + c4];
        float4 ah = xh4[(base + row * NN) * 32 + c4];
        __half2* dh = (__half2*)(X1 + row * HP + c4 * 4);
        dh[0] = __floats2half2_rn(ah.x + tval.x, ah.y + tval.y);
        dh[1] = __floats2half2_rn(ah.z + tval.z, ah.w + tval.w);
        float4 al = xl4[(base + row * NN) * 32 + c4];
        __half2* dl = (__half2*)(X2 + row * HP + c4 * 4);
        dl[0] = __floats2half2_rn(al.x + tval.x, al.y + tval.y);
        dl[1] = __floats2half2_rn(al.z + tval.z, al.w + tval.w);
    }
    for (int v = tid; v < 2048; v += 256) {
        int row = v >> 4;
        int q16 = v & 15;
        ((uint4*)(W0 + row * HP))[q16] = ((const uint4*)g_wkh16)[row * 16 + q16];
        ((uint4*)(W1 + row * HP))[q16] = ((const uint4*)g_wvh16)[row * 16 + q16];
    }
    __syncthreads();

    // ---- K and V GEMMs back-to-back ----
    float accK[4][4][4] = {};
    mma_tile(X1, W0, accK);
    float accV[4][4][4] = {};
    mma_tile(X1, W1, accV);
    __syncthreads();                 // all W0/X1 reads done

    store_tile(Ks, accK, bkh, true);
    store_tile(Vs, accV, bvh, true);
    for (int v = tid; v < 2048; v += 256) {
        int row = v >> 4;
        int q16 = v & 15;
        ((uint4*)(W0 + row * HP))[q16] = ((const uint4*)g_wq16)[row * 16 + q16];
    }
    __syncthreads();

    // ---- Q GEMM ----
    float accQ[4][4][4] = {};
    mma_tile(X2, W0, accQ);
    __syncthreads();                 // (X1 free since first sync; ensure ordering)
    store_tile(X1, accQ, bq, false); // Q -> X1
    __syncthreads();                 // Q/K/V visible

    // ---- causal attention ----
    switch (w) {
        case 0: attn_warp<1>(X1, Ks, Vs, base, 0, lane); break;
        case 1: attn_warp<2>(X1, Ks, Vs, base, 1, lane); break;
        case 2: attn_warp<3>(X1, Ks, Vs, base, 2, lane); break;
        case 3: attn_warp<4>(X1, Ks, Vs, base, 3, lane); break;
        case 4: attn_warp<5>(X1, Ks, Vs, base, 4, lane); break;
        case 5: attn_warp<6>(X1, Ks, Vs, base, 5, lane); break;
        case 6: attn_warp<7>(X1, Ks, Vs, base, 6, lane); break;
        default: attn_warp<8>(X1, Ks, Vs, base, 7, lane); break;
    }
}

// =====================================================================
// Kernel 2 (fused proj+ffn), 2 CTAs/SM:
//   val = attn@Wo + bo + (xl+te); ln1 = LN(val)  [residual in registers]
//   h = relu(ln1@Wf1+bf1); h2 = h@Wf2+bf2; out = LN(h2 + ln1)
// =====================================================================
__global__ __launch_bounds__(256, 2) void tail_kernel(
    float* __restrict__ outp,
    const float* __restrict__ xl, const float* __restrict__ te,
    const float* __restrict__ bo, const float* __restrict__ bf1,
    const float* __restrict__ bf2)
{
    extern __shared__ char smraw[];
    __half* A1 = (__half*)smraw;          // attn tile, then ln1 (f16)
    __half* A2 = A1 + 128 * HP;           // h (f16)
    __half* Wb = A2 + 128 * HP;           // current weight
    float* red1 = (float*)(Wb + 128 * HP);   // [128][4] row sums
    float* red2 = red1 + 512;                // [128][4] row sumsq
    // total: 3*34816 + 4096*2 = 112640

    const int m0 = blockIdx.x * 128;
    const int tid = threadIdx.x;
    const float* teRow = te + (m0 / NN) * FF;

    for (int v = tid; v < 2048; v += 256) {
        int row = v >> 4;
        int q16 = v & 15;
        ((uint4*)(A1 + row * HP))[q16] = ((const uint4*)(g_attn + (m0 + row) * FF))[q16];
        ((uint4*)(Wb + row * HP))[q16] = ((const uint4*)g_wo16)[row * 16 + q16];
    }
    __syncthreads();

    const int lane = tid & 31;
    const int warp = tid >> 5;
    const int wy = warp >> 2;
    const int wx = warp & 3;
    const int gid = lane >> 2;
    const int tig = lane & 3;

    // ---- proj GEMM ----
    float acc[4][4][4] = {};
    mma_tile(A1, Wb, acc);
    __syncthreads();   // A1/Wb reads done

    // ---- acc += bo + xl + te ; LN1 partial sums ----
    #pragma unroll
    for (int i = 0; i < 4; ++i) {
        int rlo = wy * 64 + i * 16 + gid;
        int rhi = rlo + 8;
        float s1lo = 0.f, s2lo = 0.f, s1hi = 0.f, s2hi = 0.f;
        #pragma unroll
        for (int j = 0; j < 4; ++j) {
            int col = wx * 32 + j * 8 + tig * 2;
            float2 bv = *(const float2*)(bo + col);
            float2 x0 = *(const float2*)(xl + (m0 + rlo) * FF + col);
            float2 x1 = *(const float2*)(xl + (m0 + rhi) * FF + col);
            float2 t0 = *(const float2*)(teRow + col);
            float v0 = acc[i][j][0] + bv.x + x0.x + t0.x;
            float v1 = acc[i][j][1] + bv.y + x0.y + t0.y;
            float v2 = acc[i][j][2] + bv.x + x1.x + t0.x;
            float v3 = acc[i][j][3] + bv.y + x1.y + t0.y;
            acc[i][j][0] = v0; acc[i][j][1] = v1;
            acc[i][j][2] = v2; acc[i][j][3] = v3;
            s1lo += v0 + v1; s2lo += v0 * v0 + v1 * v1;
            s1hi += v2 + v3; s2hi += v2 * v2 + v3 * v3;
        }
        #pragma unroll
        for (int o = 1; o <= 2; o <<= 1) {
            s1lo += __shfl_xor_sync(0xffffffffu, s1lo, o);
            s2lo += __shfl_xor_sync(0xffffffffu, s2lo, o);
            s1hi += __shfl_xor_sync(0xffffffffu, s1hi, o);
            s2hi += __shfl_xor_sync(0xffffffffu, s2hi, o);
        }
        if (tig == 0) {
            red1[rlo * 4 + wx] = s1lo; red2[rlo * 4 + wx] = s2lo;
            red1[rhi * 4 + wx] = s1hi; red2[rhi * 4 + wx] = s2hi;
        }
    }
    __syncthreads();

    // ---- LN1 finalize: write ln1 (f16) to A1; stage Wf1 ----
    #pragma unroll
    for (int i = 0; i < 4; ++i) {
        int rlo = wy * 64 + i * 16 + gid;
        int rhi = rlo + 8;
        float mlo = (red1[rlo * 4] + red1[rlo * 4 + 1] + red1[rlo * 4 + 2] + red1[rlo * 4 + 3]) * 0.0078125f;
        float vlo = (red2[rlo * 4] + red2[rlo * 4 + 1] + red2[rlo * 4 + 2] + red2[rlo * 4 + 3]) * 0.0078125f - mlo * mlo;
        float rslo = rsqrtf(vlo + 1e-5f);
        float mhi = (red1[rhi * 4] + red1[rhi * 4 + 1] + red1[rhi * 4 + 2] + red1[rhi * 4 + 3]) * 0.0078125f;
        float vhi = (red2[rhi * 4] + red2[rhi * 4 + 1] + red2[rhi * 4 + 2] + red2[rhi * 4 + 3]) * 0.0078125f - mhi * mhi;
        float rshi = rsqrtf(vhi + 1e-5f);
        #pragma unroll
        for (int j = 0; j < 4; ++j) {
            int col = wx * 32 + j * 8 + tig * 2;
            *(__half2*)(A1 + rlo * HP + col) =
                __floats2half2_rn((acc[i][j][0] - mlo) * rslo, (acc[i][j][1] - mlo) * rslo);
            *(__half2*)(A1 + rhi * HP + col) =
                __floats2half2_rn((acc[i][j][2] - mhi) * rshi, (acc[i][j][3] - mhi) * rshi);
        }
    }
    for (int v = tid; v < 2048; v += 256) {
        int row = v >> 4;
        int q16 = v & 15;
        ((uint4*)(Wb + row * HP))[q16] = ((const uint4*)g_wf116)[row * 16 + q16];
    }
    __syncthreads();

    // ---- FFN GEMM 1 ----
    float acc2[4][4][4] = {};
    mma_tile(A1, Wb, acc2);
    __syncthreads();
    store_tile(A2, acc2, bf1, true);
    for (int v = tid; v < 2048; v += 256) {
        int row = v >> 4;
        int q16 = v & 15;
        ((uint4*)(Wb + row * HP))[q16] = ((const uint4*)g_wf216)[row * 16 + q16];
    }
    __syncthreads();

    // ---- FFN GEMM 2 ----
    float acc3[4][4][4] = {};
    mma_tile(A2, Wb, acc3);

    // ---- acc3 += bf2 + ln1(A1); LN2 partials ----
    #pragma unroll
    for (int i = 0; i < 4; ++i) {
        int rlo = wy * 64 + i * 16 + gid;
        int rhi = rlo + 8;
        float s1lo = 0.f, s2lo = 0.f, s1hi = 0.f, s2hi = 0.f;
        #pragma unroll
        for (int j = 0; j < 4; ++j) {
            int col = wx * 32 + j * 8 + tig * 2;
            float2 bv = *(const float2*)(bf2 + col);
            float2 l0 = __half22float2(*(const __half2*)(A1 + rlo * HP + col));
            float2 l1 = __half22float2(*(const __half2*)(A1 + rhi * HP + col));
            float v0 = acc3[i][j][0] + bv.x + l0.x;
            float v1 = acc3[i][j][1] + bv.y + l0.y;
            float v2 = acc3[i][j][2] + bv.x + l1.x;
            float v3 = acc3[i][j][3] + bv.y + l1.y;
            acc3[i][j][0] = v0; acc3[i][j][1] = v1;
            acc3[i][j][2] = v2; acc3[i][j][3] = v3;
            s1lo += v0 + v1; s2lo += v0 * v0 + v1 * v1;
            s1hi += v2 + v3; s2hi += v2 * v2 + v3 * v3;
        }
        #pragma unroll
        for (int o = 1; o <= 2; o <<= 1) {
            s1lo += __shfl_xor_sync(0xffffffffu, s1lo, o);
            s2lo += __shfl_xor_sync(0xffffffffu, s2lo, o);
            s1hi += __shfl_xor_sync(0xffffffffu, s1hi, o);
            s2hi += __shfl_xor_sync(0xffffffffu, s2hi, o);
        }
        if (tig == 0) {
            red1[rlo * 4 + wx] = s1lo; red2[rlo * 4 + wx] = s2lo;
            red1[rhi * 4 + wx] = s1hi; red2[rhi * 4 + wx] = s2hi;
        }
    }
    __syncthreads();

    // ---- LN2 finalize -> output ----
    #pragma unroll
    for (int i = 0; i < 4; ++i) {
        int rlo = wy * 64 + i * 16 + gid;
        int rhi = rlo + 8;
        float mlo = (red1[rlo * 4] + red1[rlo * 4 + 1] + red1[rlo * 4 + 2] + red1[rlo * 4 + 3]) * 0.0078125f;
        float vlo = (red2[rlo * 4] + red2[rlo * 4 + 1] + red2[rlo * 4 + 2] + red2[rlo * 4 + 3]) * 0.0078125f - mlo * mlo;
        float rslo = rsqrtf(vlo + 1e-5f);
        float mhi = (red1[rhi * 4] + red1[rhi * 4 + 1] + red1[rhi * 4 + 2] + red1[rhi * 4 + 3]) * 0.0078125f;
        float vhi = (red2[rhi * 4] + red2[rhi * 4 + 1] + red2[rhi * 4 + 2] + red2[rhi * 4 + 3]) * 0.0078125f - mhi * mhi;
        float rshi = rsqrtf(vhi + 1e-5f);
        #pragma unroll
        for (int j = 0; j < 4; ++j) {
            int col = wx * 32 + j * 8 + tig * 2;
            float2 o0, o1;
            o0.x = (acc3[i][j][0] - mlo) * rslo;
            o0.y = (acc3[i][j][1] - mlo) * rslo;
            o1.x = (acc3[i][j][2] - mhi) * rshi;
            o1.y = (acc3[i][j][3] - mhi) * rshi;
            *(float2*)(outp + (m0 + rlo) * FF + col) = o0;
            *(float2*)(outp + (m0 + rhi) * FF + col) = o1;
        }
    }
}

// =====================================================================
extern "C" void kernel_launch(void* const* d_in, const int* in_sizes, int n_in,
                              void* d_out, int out_size)
{
    const float* xl  = (const float*)d_in[0];
    const float* xh  = (const float*)d_in[1];
    const float* te  = (const float*)d_in[2];
    const float* Wq  = (const float*)d_in[3];
    const float* bq  = (const float*)d_in[4];
    const float* Wkh = (const float*)d_in[5];
    const float* bkh = (const float*)d_in[6];
    const float* Wvh = (const float*)d_in[7];
    const float* bvh = (const float*)d_in[8];
    const float* Wo  = (const float*)d_in[9];
    const float* bo  = (const float*)d_in[10];
    const float* Wf1 = (const float*)d_in[11];
    const float* bf1 = (const float*)d_in[12];
    const float* Wf2 = (const float*)d_in[13];
    const float* bf2 = (const float*)d_in[14];
    float* outp = (float*)d_out;

    const int smFused = 6 * 128 * HP * 2;                     // 208896
    const int smTail  = 3 * 128 * HP * 2 + 2 * 4096;          // 112640

    cudaFuncSetAttribute(fused_attn_kernel, cudaFuncAttributeMaxDynamicSharedMemorySize, smFused);
    cudaFuncSetAttribute(tail_kernel,       cudaFuncAttributeMaxDynamicSharedMemorySize, smTail);

    conv_kernel<<<64, 256>>>(Wq, Wkh, Wvh, Wo, Wf1, Wf2);
    fused_attn_kernel<<<BB * NN, 256, smFused>>>(xl, xh, te, bq, bkh, bvh);
    tail_kernel<<<MTOT / 128, 256, smTail>>>(outp, xl, te, bo, bf1, bf2);
}